// round 1
// baseline (speedup 1.0000x reference)
#include <cuda_runtime.h>

#define D_MODEL 1024
#define NHEAD   16
#define DKH     64
#define BB      2
#define SSEQ    2048
#define NTOK    (BB * SSEQ)      /* 4096 */
#define BHN     (BB * NHEAD)     /* 32   */

// Scratch (device globals: allocation-free per harness rules)
__device__ float g_Q[(size_t)NTOK * D_MODEL];
__device__ float g_K[(size_t)NTOK * D_MODEL];
__device__ float g_V[(size_t)NTOK * D_MODEL];
__device__ float g_AO[(size_t)NTOK * D_MODEL];

// ---------------------------------------------------------------------------
// Core: C[m0:+128, n0:+128] = alpha * A * B^T
// A [*,K] row-major lda, B [*,K] row-major ldb (both K-contiguous -> NT GEMM)
// Requires K % 16 == 0, all pointers 16B-aligned, lda/ldb/ldc % 4 == 0.
// 256 threads, 8x8 micro-tile per thread.
// ---------------------------------------------------------------------------
__device__ __forceinline__ void gemm_nt_core(
    const float* __restrict__ A, const float* __restrict__ Bm, float* __restrict__ C,
    int K, int lda, int ldb, int ldc, float alpha, int m0, int n0)
{
    __shared__ float As[16][128];
    __shared__ float Bs[16][128];
    const int tid = threadIdx.x;
    const int tx = tid & 15;   // n micro-group
    const int ty = tid >> 4;   // m micro-group

    float acc[8][8];
#pragma unroll
    for (int i = 0; i < 8; i++)
#pragma unroll
        for (int j = 0; j < 8; j++) acc[i][j] = 0.f;

    for (int k0 = 0; k0 < K; k0 += 16) {
#pragma unroll
        for (int i = 0; i < 2; i++) {
            int idx = tid + i * 256;        // float4 index 0..511
            int row = idx >> 2;             // 0..127
            int c4  = (idx & 3) * 4;        // 0,4,8,12
            float4 va = *(const float4*)(A + (size_t)(m0 + row) * lda + k0 + c4);
            As[c4 + 0][row] = va.x; As[c4 + 1][row] = va.y;
            As[c4 + 2][row] = va.z; As[c4 + 3][row] = va.w;
            float4 vb = *(const float4*)(Bm + (size_t)(n0 + row) * ldb + k0 + c4);
            Bs[c4 + 0][row] = vb.x; Bs[c4 + 1][row] = vb.y;
            Bs[c4 + 2][row] = vb.z; Bs[c4 + 3][row] = vb.w;
        }
        __syncthreads();
#pragma unroll
        for (int kk = 0; kk < 16; kk++) {
            float a[8], b[8];
            *(float4*)&a[0] = *(const float4*)&As[kk][ty * 8];
            *(float4*)&a[4] = *(const float4*)&As[kk][ty * 8 + 4];
            *(float4*)&b[0] = *(const float4*)&Bs[kk][tx * 8];
            *(float4*)&b[4] = *(const float4*)&Bs[kk][tx * 8 + 4];
#pragma unroll
            for (int i = 0; i < 8; i++)
#pragma unroll
                for (int j = 0; j < 8; j++)
                    acc[i][j] += a[i] * b[j];
        }
        __syncthreads();
    }

#pragma unroll
    for (int i = 0; i < 8; i++) {
        float* cp = C + (size_t)(m0 + ty * 8 + i) * ldc + n0 + tx * 8;
        float4 o0 = make_float4(alpha * acc[i][0], alpha * acc[i][1],
                                alpha * acc[i][2], alpha * acc[i][3]);
        float4 o1 = make_float4(alpha * acc[i][4], alpha * acc[i][5],
                                alpha * acc[i][6], alpha * acc[i][7]);
        *(float4*)cp       = o0;
        *(float4*)(cp + 4) = o1;
    }
}

// ---------------------------------------------------------------------------
// Projection / output GEMM: C = A @ W^T   (M=4096, N=1024, K=1024)
// ---------------------------------------------------------------------------
__global__ __launch_bounds__(256)
void proj_kernel(const float* __restrict__ A, const float* __restrict__ W,
                 float* __restrict__ C)
{
    gemm_nt_core(A, W, C, D_MODEL, D_MODEL, D_MODEL, D_MODEL, 1.0f,
                 blockIdx.y * 128, blockIdx.x * 128);
}

// ---------------------------------------------------------------------------
// Scores = Qh @ Kh^T / sqrt(dk), per (b,h).  grid(16,16,32)
// ---------------------------------------------------------------------------
__global__ __launch_bounds__(256)
void qk_kernel(float* __restrict__ attnw)
{
    const int z = blockIdx.z;
    const int b = z >> 4;
    const int h = z & 15;
    const float* Aq = g_Q + (size_t)b * SSEQ * D_MODEL + h * DKH;
    const float* Bk = g_K + (size_t)b * SSEQ * D_MODEL + h * DKH;
    float* Cp = attnw + (size_t)z * SSEQ * SSEQ;
    gemm_nt_core(Aq, Bk, Cp, DKH, D_MODEL, D_MODEL, SSEQ, 0.125f,
                 blockIdx.y * 128, blockIdx.x * 128);
}

// ---------------------------------------------------------------------------
// In-place softmax over each row of attn_weights. One block per row (2048).
// ---------------------------------------------------------------------------
__global__ __launch_bounds__(256)
void softmax_kernel(float* __restrict__ P)
{
    float* p = P + (size_t)blockIdx.x * SSEQ;
    const int tid = threadIdx.x;
    __shared__ float sbuf[8];
    __shared__ float sres;

    float v[8];
    float m = -3.402823e38f;
#pragma unroll
    for (int i = 0; i < 8; i++) { v[i] = p[tid + i * 256]; m = fmaxf(m, v[i]); }
#pragma unroll
    for (int o = 16; o > 0; o >>= 1) m = fmaxf(m, __shfl_xor_sync(0xffffffffu, m, o));
    if ((tid & 31) == 0) sbuf[tid >> 5] = m;
    __syncthreads();
    if (tid == 0) {
        float mm = sbuf[0];
#pragma unroll
        for (int w = 1; w < 8; w++) mm = fmaxf(mm, sbuf[w]);
        sres = mm;
    }
    __syncthreads();
    m = sres;

    float l = 0.f;
#pragma unroll
    for (int i = 0; i < 8; i++) { v[i] = __expf(v[i] - m); l += v[i]; }
#pragma unroll
    for (int o = 16; o > 0; o >>= 1) l += __shfl_xor_sync(0xffffffffu, l, o);
    __syncthreads();                 // protect sbuf/sres reuse
    if ((tid & 31) == 0) sbuf[tid >> 5] = l;
    __syncthreads();
    if (tid == 0) {
        float ll = 0.f;
#pragma unroll
        for (int w = 0; w < 8; w++) ll += sbuf[w];
        sres = 1.f / ll;
    }
    __syncthreads();
    const float inv = sres;
#pragma unroll
    for (int i = 0; i < 8; i++) p[tid + i * 256] = v[i] * inv;
}

// ---------------------------------------------------------------------------
// attn_out(h slice) = P @ Vh, per (b,h).  NN GEMM: M=2048, N=64, K=2048.
// grid(1, 16, 32), 256 threads, 8x4 micro-tile.
// ---------------------------------------------------------------------------
__global__ __launch_bounds__(256)
void av_kernel(const float* __restrict__ attnw)
{
    const int z = blockIdx.z;
    const int b = z >> 4;
    const int h = z & 15;
    const float* A  = attnw + (size_t)z * SSEQ * SSEQ;                 // [2048,2048]
    const float* Bv = g_V  + (size_t)b * SSEQ * D_MODEL + h * DKH;     // [k][d], ld=1024
    float* C        = g_AO + (size_t)b * SSEQ * D_MODEL + h * DKH;     // ld=1024

    __shared__ float As[16][128];
    __shared__ float Bs[16][64];
    const int tid = threadIdx.x;
    const int tx = tid & 15;   // n group (4 cols each)
    const int ty = tid >> 4;   // m group (8 rows each)
    const int m0 = blockIdx.y * 128;

    float acc[8][4];
#pragma unroll
    for (int i = 0; i < 8; i++)
#pragma unroll
        for (int j = 0; j < 4; j++) acc[i][j] = 0.f;

    for (int k0 = 0; k0 < SSEQ; k0 += 16) {
#pragma unroll
        for (int i = 0; i < 2; i++) {
            int idx = tid + i * 256;
            int row = idx >> 2;
            int c4  = (idx & 3) * 4;
            float4 va = *(const float4*)(A + (size_t)(m0 + row) * SSEQ + k0 + c4);
            As[c4 + 0][row] = va.x; As[c4 + 1][row] = va.y;
            As[c4 + 2][row] = va.z; As[c4 + 3][row] = va.w;
        }
        {
            int row = tid >> 4;            // 0..15 (k within tile)
            int c4  = (tid & 15) * 4;      // 0..60 (d)
            float4 vb = *(const float4*)(Bv + (size_t)(k0 + row) * D_MODEL + c4);
            *(float4*)&Bs[row][c4] = vb;
        }
        __syncthreads();
#pragma unroll
        for (int kk = 0; kk < 16; kk++) {
            float a[8], bq[4];
            *(float4*)&a[0]  = *(const float4*)&As[kk][ty * 8];
            *(float4*)&a[4]  = *(const float4*)&As[kk][ty * 8 + 4];
            *(float4*)&bq[0] = *(const float4*)&Bs[kk][tx * 4];
#pragma unroll
            for (int i = 0; i < 8; i++)
#pragma unroll
                for (int j = 0; j < 4; j++)
                    acc[i][j] += a[i] * bq[j];
        }
        __syncthreads();
    }

#pragma unroll
    for (int i = 0; i < 8; i++) {
        float* cp = C + (size_t)(m0 + ty * 8 + i) * D_MODEL + tx * 4;
        *(float4*)cp = make_float4(acc[i][0], acc[i][1], acc[i][2], acc[i][3]);
    }
}

// ---------------------------------------------------------------------------
extern "C" void kernel_launch(void* const* d_in, const int* in_sizes, int n_in,
                              void* d_out, int out_size)
{
    const float* q  = (const float*)d_in[0];
    const float* k  = (const float*)d_in[1];
    const float* v  = (const float*)d_in[2];
    const float* Wq = (const float*)d_in[3];
    const float* Wk = (const float*)d_in[4];
    const float* Wv = (const float*)d_in[5];
    const float* Wo = (const float*)d_in[6];

    float* out   = (float*)d_out;                       // [B,S,D] = 4194304 floats
    float* attnw = out + (size_t)NTOK * D_MODEL;        // [B,H,S,S] follows

    float *pQ, *pK, *pV, *pAO;
    cudaGetSymbolAddress((void**)&pQ,  g_Q);
    cudaGetSymbolAddress((void**)&pK,  g_K);
    cudaGetSymbolAddress((void**)&pV,  g_V);
    cudaGetSymbolAddress((void**)&pAO, g_AO);

    dim3 blk(256);
    dim3 gp(D_MODEL / 128, NTOK / 128);        // (8, 32)
    proj_kernel<<<gp, blk>>>(q, Wq, pQ);
    proj_kernel<<<gp, blk>>>(k, Wk, pK);
    proj_kernel<<<gp, blk>>>(v, Wv, pV);

    dim3 gqk(SSEQ / 128, SSEQ / 128, BHN);     // (16, 16, 32)
    qk_kernel<<<gqk, blk>>>(attnw);

    softmax_kernel<<<BHN * SSEQ, blk>>>(attnw);

    dim3 gav(1, SSEQ / 128, BHN);              // (1, 16, 32)
    av_kernel<<<gav, blk>>>(attnw);

    proj_kernel<<<gp, blk>>>(pAO, Wo, out);    // output = attn_out @ W_o^T
}

// round 11
// speedup vs baseline: 1.6756x; 1.6756x over previous
#include <cuda_runtime.h>
#include <cuda_bf16.h>
#include <cstdint>

#define D_MODEL 1024
#define NHEAD   16
#define DKH     64
#define BB      2
#define SSEQ    2048
#define NTOK    (BB * SSEQ)      /* 4096 */
#define BHN     (BB * NHEAD)     /* 32   */

// ---------------------------------------------------------------------------
// PTX helpers: ldmatrix + mma.sync (sm_80+, no arch-'a' features)
// ---------------------------------------------------------------------------
__device__ __forceinline__ uint32_t smem_u32(const void* p) {
    uint32_t a;
    asm("{ .reg .u64 t; cvta.to.shared.u64 t, %1; cvt.u32.u64 %0, t; }" : "=r"(a) : "l"(p));
    return a;
}

__device__ __forceinline__ void ldsm_x4(uint32_t* r, uint32_t addr) {
    asm volatile("ldmatrix.sync.aligned.m8n8.x4.shared.b16 {%0,%1,%2,%3}, [%4];"
                 : "=r"(r[0]), "=r"(r[1]), "=r"(r[2]), "=r"(r[3]) : "r"(addr));
}
__device__ __forceinline__ void ldsm_x2(uint32_t& r0, uint32_t& r1, uint32_t addr) {
    asm volatile("ldmatrix.sync.aligned.m8n8.x2.shared.b16 {%0,%1}, [%2];"
                 : "=r"(r0), "=r"(r1) : "r"(addr));
}
__device__ __forceinline__ void mma16816(float* c, const uint32_t* a, uint32_t b0, uint32_t b1) {
    asm volatile(
        "mma.sync.aligned.m16n8k16.row.col.f32.bf16.bf16.f32 "
        "{%0,%1,%2,%3}, {%4,%5,%6,%7}, {%8,%9}, {%0,%1,%2,%3};"
        : "+f"(c[0]), "+f"(c[1]), "+f"(c[2]), "+f"(c[3])
        : "r"(a[0]), "r"(a[1]), "r"(a[2]), "r"(a[3]), "r"(b0), "r"(b1));
}

// ---------------------------------------------------------------------------
// Device scratch (bf16 hi/lo splits + fp32 V)
// ---------------------------------------------------------------------------
__device__ __nv_bfloat16 g_qin_h[NTOK * D_MODEL], g_qin_l[NTOK * D_MODEL];
__device__ __nv_bfloat16 g_kin_h[NTOK * D_MODEL], g_kin_l[NTOK * D_MODEL];
__device__ __nv_bfloat16 g_vin_h[NTOK * D_MODEL], g_vin_l[NTOK * D_MODEL];
__device__ __nv_bfloat16 g_wq_h[D_MODEL * D_MODEL], g_wq_l[D_MODEL * D_MODEL];
__device__ __nv_bfloat16 g_wk_h[D_MODEL * D_MODEL], g_wk_l[D_MODEL * D_MODEL];
__device__ __nv_bfloat16 g_wv_h[D_MODEL * D_MODEL], g_wv_l[D_MODEL * D_MODEL];
__device__ __nv_bfloat16 g_wo_h[D_MODEL * D_MODEL], g_wo_l[D_MODEL * D_MODEL];
__device__ __nv_bfloat16 g_Qh[NTOK * D_MODEL], g_Ql[NTOK * D_MODEL];
__device__ __nv_bfloat16 g_Kh[NTOK * D_MODEL], g_Kl[NTOK * D_MODEL];
__device__ float         g_Vf[NTOK * D_MODEL];
__device__ __nv_bfloat16 g_Vth[BHN * DKH * SSEQ], g_Vtl[BHN * DKH * SSEQ];
__device__ __nv_bfloat16 g_AOh[NTOK * D_MODEL], g_AOl[NTOK * D_MODEL];

// ---------------------------------------------------------------------------
// Elementwise split: x -> (hi, lo) bf16
// ---------------------------------------------------------------------------
__global__ __launch_bounds__(256)
void split_kernel(const float* __restrict__ x, __nv_bfloat16* __restrict__ h,
                  __nv_bfloat16* __restrict__ l, int n)
{
    int i = (blockIdx.x * 256 + threadIdx.x) * 4;
    if (i >= n) return;
    float4 v = *(const float4*)(x + i);
    __nv_bfloat16 h0 = __float2bfloat16(v.x), h1 = __float2bfloat16(v.y);
    __nv_bfloat16 h2 = __float2bfloat16(v.z), h3 = __float2bfloat16(v.w);
    __nv_bfloat16 l0 = __float2bfloat16(v.x - __bfloat162float(h0));
    __nv_bfloat16 l1 = __float2bfloat16(v.y - __bfloat162float(h1));
    __nv_bfloat16 l2 = __float2bfloat16(v.z - __bfloat162float(h2));
    __nv_bfloat16 l3 = __float2bfloat16(v.w - __bfloat162float(h3));
    __nv_bfloat162* hp = (__nv_bfloat162*)(h + i);
    hp[0] = __nv_bfloat162(h0, h1); hp[1] = __nv_bfloat162(h2, h3);
    __nv_bfloat162* lp = (__nv_bfloat162*)(l + i);
    lp[0] = __nv_bfloat162(l0, l1); lp[1] = __nv_bfloat162(l2, l3);
}

// ---------------------------------------------------------------------------
// V transpose + split: g_Vf[token][dmodel] -> Vt[bh][d][s] hi/lo
// ---------------------------------------------------------------------------
__global__ __launch_bounds__(256)
void vtrans_kernel(const float* __restrict__ V, __nv_bfloat16* __restrict__ Vh,
                   __nv_bfloat16* __restrict__ Vl)
{
    __shared__ float t[32][33];
    const int bh = blockIdx.z, b = bh >> 4, h = bh & 15;
    const int s0 = blockIdx.x * 32, d0 = blockIdx.y * 32;
    for (int i = threadIdx.y; i < 32; i += 8)
        t[i][threadIdx.x] = V[(size_t)(b * SSEQ + s0 + i) * D_MODEL + h * DKH + d0 + threadIdx.x];
    __syncthreads();
    for (int i = threadIdx.y; i < 32; i += 8) {
        float v = t[threadIdx.x][i];
        size_t o = (size_t)bh * DKH * SSEQ + (size_t)(d0 + i) * SSEQ + s0 + threadIdx.x;
        __nv_bfloat16 hh = __float2bfloat16(v);
        Vh[o] = hh;
        Vl[o] = __float2bfloat16(v - __bfloat162float(hh));
    }
}

// ---------------------------------------------------------------------------
// HMMA (mma.sync m16n8k16 bf16) GEMM.  M-tile=128, N-tile=NT, K-tile=32.
// C = alpha * (Ah+Al) @ (Bh+Bl)^T  via 3 accumulated MMA terms.
// A_FP32: A operand fp32 in gmem, split to hi/lo in SMEM on load.
// OUT_SPLIT: write Ch/Cl bf16 hi/lo; else fp32 Cf.
// 256 threads = 8 warps; NT=128: 2x4 warp grid (64x32 warp tile);
//                        NT=64 : 4x2 warp grid (32x32 warp tile).
// ---------------------------------------------------------------------------
template<int NT, bool A_FP32, bool OUT_SPLIT>
__global__ __launch_bounds__(256)
void mma_gemm(const void* __restrict__ A0, const void* __restrict__ A1, size_t lda,
              const __nv_bfloat16* __restrict__ Bh, const __nv_bfloat16* __restrict__ Bl,
              size_t ldb, int kTiles, float alpha,
              float* __restrict__ Cf, __nv_bfloat16* __restrict__ Ch,
              __nv_bfloat16* __restrict__ Cl, size_t ldc,
              size_t aB, size_t aH, size_t bB, size_t bH, size_t cB, size_t cH)
{
    constexpr int KT = 32;                 // k per smem tile (bf16)
    constexpr int KS = KT + 8;             // padded row stride (elems), 80 B
    constexpr int WARPS_M = (NT == 128) ? 2 : 4;
    constexpr int WARPS_N = 8 / WARPS_M;
    constexpr int WTM = 128 / WARPS_M;     // 64 or 32
    constexpr int WTN = NT / WARPS_N;      // 32
    constexpr int MF = WTM / 16;           // 4 or 2
    constexpr int NF = WTN / 8;            // 4

    __shared__ __nv_bfloat16 sAh[128 * KS], sAl[128 * KS];
    __shared__ __nv_bfloat16 sBh[NT * KS],  sBl[NT * KS];

    const int tid = threadIdx.x;
    const int w = tid >> 5, lane = tid & 31;
    const int wm = w % WARPS_M, wn = w / WARPS_M;
    const int zb = blockIdx.z >> 4, zh = blockIdx.z & 15;
    const int m0 = blockIdx.y * 128, n0 = blockIdx.x * NT;

    const size_t aOff = (size_t)zb * aB + (size_t)zh * aH;
    const size_t bOff = (size_t)zb * bB + (size_t)zh * bH;
    const size_t cOff = (size_t)zb * cB + (size_t)zh * cH;

    const uint32_t uAh = smem_u32(sAh), uAl = smem_u32(sAl);
    const uint32_t uBh = smem_u32(sBh), uBl = smem_u32(sBl);

    float acc[MF][NF][4];
#pragma unroll
    for (int i = 0; i < MF; i++)
#pragma unroll
        for (int j = 0; j < NF; j++)
#pragma unroll
            for (int e = 0; e < 4; e++) acc[i][j][e] = 0.f;

    // ldmatrix source addresses (fixed per thread)
    const int a_g = lane >> 3, a_r = lane & 7;
    const int a_row_off = (a_g & 1) * 8 + a_r;      // + mi*16 + wm*WTM
    const int a_col_off = (a_g >> 1) * 8;           // + k16
    const int b_row_off = lane & 7;                 // + ni*8 + wn*WTN
    const int b_col_off = ((lane >> 3) & 1) * 8;    // + k16

    for (int kt = 0; kt < kTiles; kt++) {
        // ---- A tile: 128 x 32 bf16 (hi/lo) ----
        if (!A_FP32) {
            const __nv_bfloat16* Ahp = (const __nv_bfloat16*)A0 + aOff;
            const __nv_bfloat16* Alp = (const __nv_bfloat16*)A1 + aOff;
#pragma unroll
            for (int it = 0; it < 2; it++) {
                int i = tid + it * 256;            // 512 uint4
                int r = i >> 2, c8 = (i & 3) * 8;
                size_t g = (size_t)(m0 + r) * lda + kt * KT + c8;
                *(uint4*)&sAh[r * KS + c8] = *(const uint4*)(Ahp + g);
                *(uint4*)&sAl[r * KS + c8] = *(const uint4*)(Alp + g);
            }
        } else {
            const float* Af = (const float*)A0 + aOff;
#pragma unroll
            for (int it = 0; it < 4; it++) {
                int i = tid + it * 256;            // 1024 float4
                int r = i >> 3, c4 = (i & 7) * 4;
                float4 v = *(const float4*)(Af + (size_t)(m0 + r) * lda + kt * KT + c4);
                __nv_bfloat16 h0 = __float2bfloat16(v.x), h1 = __float2bfloat16(v.y);
                __nv_bfloat16 h2 = __float2bfloat16(v.z), h3 = __float2bfloat16(v.w);
                __nv_bfloat16 l0 = __float2bfloat16(v.x - __bfloat162float(h0));
                __nv_bfloat16 l1 = __float2bfloat16(v.y - __bfloat162float(h1));
                __nv_bfloat16 l2 = __float2bfloat16(v.z - __bfloat162float(h2));
                __nv_bfloat16 l3 = __float2bfloat16(v.w - __bfloat162float(h3));
                uint2 hp, lp;
                __nv_bfloat162 t0(h0, h1), t1(h2, h3);
                hp.x = *(uint32_t*)&t0; hp.y = *(uint32_t*)&t1;
                __nv_bfloat162 t2(l0, l1), t3(l2, l3);
                lp.x = *(uint32_t*)&t2; lp.y = *(uint32_t*)&t3;
                *(uint2*)&sAh[r * KS + c4] = hp;
                *(uint2*)&sAl[r * KS + c4] = lp;
            }
        }
        // ---- B tile: NT x 32 bf16 (hi/lo) ----
        {
#pragma unroll
            for (int it = 0; it < NT / 64; it++) {
                int i = tid + it * 256;            // NT*4 uint4
                int r = i >> 2, c8 = (i & 3) * 8;
                size_t g = (size_t)(n0 + r) * ldb + kt * KT + c8;
                *(uint4*)&sBh[r * KS + c8] = *(const uint4*)(Bh + bOff + g);
                *(uint4*)&sBl[r * KS + c8] = *(const uint4*)(Bl + bOff + g);
            }
        }
        __syncthreads();

#pragma unroll
        for (int k16 = 0; k16 < KT; k16 += 16) {
            uint32_t aH[MF][4], aL[MF][4];
#pragma unroll
            for (int mi = 0; mi < MF; mi++) {
                uint32_t off = (uint32_t)((wm * WTM + mi * 16 + a_row_off) * KS
                                          + k16 + a_col_off) * 2;
                ldsm_x4(aH[mi], uAh + off);
                ldsm_x4(aL[mi], uAl + off);
            }
#pragma unroll
            for (int ni = 0; ni < NF; ni++) {
                uint32_t off = (uint32_t)((wn * WTN + ni * 8 + b_row_off) * KS
                                          + k16 + b_col_off) * 2;
                uint32_t bh0, bh1, bl0, bl1;
                ldsm_x2(bh0, bh1, uBh + off);
                ldsm_x2(bl0, bl1, uBl + off);
#pragma unroll
                for (int mi = 0; mi < MF; mi++) {
                    mma16816(acc[mi][ni], aH[mi], bh0, bh1);   // Ah*Bh
                    mma16816(acc[mi][ni], aH[mi], bl0, bl1);   // Ah*Bl
                    mma16816(acc[mi][ni], aL[mi], bh0, bh1);   // Al*Bh
                }
            }
        }
        __syncthreads();
    }

    // ---- epilogue: fragment -> gmem ----
    const int er = lane >> 2, ec = (lane & 3) * 2;
#pragma unroll
    for (int mi = 0; mi < MF; mi++) {
#pragma unroll
        for (int ni = 0; ni < NF; ni++) {
            int row = m0 + wm * WTM + mi * 16 + er;
            int col = n0 + wn * WTN + ni * 8 + ec;
#pragma unroll
            for (int half = 0; half < 2; half++) {
                float v0 = alpha * acc[mi][ni][half * 2 + 0];
                float v1 = alpha * acc[mi][ni][half * 2 + 1];
                size_t off = cOff + (size_t)(row + half * 8) * ldc + col;
                if (OUT_SPLIT) {
                    __nv_bfloat16 h0 = __float2bfloat16(v0);
                    __nv_bfloat16 h1 = __float2bfloat16(v1);
                    __nv_bfloat16 l0 = __float2bfloat16(v0 - __bfloat162float(h0));
                    __nv_bfloat16 l1 = __float2bfloat16(v1 - __bfloat162float(h1));
                    __nv_bfloat162 hp(h0, h1), lp(l0, l1);
                    *(__nv_bfloat162*)(Ch + off) = hp;
                    *(__nv_bfloat162*)(Cl + off) = lp;
                } else {
                    *(float2*)(Cf + off) = make_float2(v0, v1);
                }
            }
        }
    }
}

// ---------------------------------------------------------------------------
// In-place row softmax (unchanged from passing baseline)
// ---------------------------------------------------------------------------
__global__ __launch_bounds__(256)
void softmax_kernel(float* __restrict__ P)
{
    float* p = P + (size_t)blockIdx.x * SSEQ;
    const int tid = threadIdx.x;
    __shared__ float sbuf[8];
    __shared__ float sres;

    float v[8];
    float m = -3.402823e38f;
#pragma unroll
    for (int i = 0; i < 8; i++) { v[i] = p[tid + i * 256]; m = fmaxf(m, v[i]); }
#pragma unroll
    for (int o = 16; o > 0; o >>= 1) m = fmaxf(m, __shfl_xor_sync(0xffffffffu, m, o));
    if ((tid & 31) == 0) sbuf[tid >> 5] = m;
    __syncthreads();
    if (tid == 0) {
        float mm = sbuf[0];
#pragma unroll
        for (int w = 1; w < 8; w++) mm = fmaxf(mm, sbuf[w]);
        sres = mm;
    }
    __syncthreads();
    m = sres;

    float l = 0.f;
#pragma unroll
    for (int i = 0; i < 8; i++) { v[i] = __expf(v[i] - m); l += v[i]; }
#pragma unroll
    for (int o = 16; o > 0; o >>= 1) l += __shfl_xor_sync(0xffffffffu, l, o);
    __syncthreads();
    if ((tid & 31) == 0) sbuf[tid >> 5] = l;
    __syncthreads();
    if (tid == 0) {
        float ll = 0.f;
#pragma unroll
        for (int w = 0; w < 8; w++) ll += sbuf[w];
        sres = 1.f / ll;
    }
    __syncthreads();
    const float inv = sres;
#pragma unroll
    for (int i = 0; i < 8; i++) p[tid + i * 256] = v[i] * inv;
}

// ---------------------------------------------------------------------------
extern "C" void kernel_launch(void* const* d_in, const int* in_sizes, int n_in,
                              void* d_out, int out_size)
{
    const float* q  = (const float*)d_in[0];
    const float* k  = (const float*)d_in[1];
    const float* v  = (const float*)d_in[2];
    const float* Wq = (const float*)d_in[3];
    const float* Wk = (const float*)d_in[4];
    const float* Wv = (const float*)d_in[5];
    const float* Wo = (const float*)d_in[6];

    float* out   = (float*)d_out;
    float* attnw = out + (size_t)NTOK * D_MODEL;

    __nv_bfloat16 *qin_h, *qin_l, *kin_h, *kin_l, *vin_h, *vin_l;
    __nv_bfloat16 *wq_h, *wq_l, *wk_h, *wk_l, *wv_h, *wv_l, *wo_h, *wo_l;
    __nv_bfloat16 *Qh, *Ql, *Kh, *Kl, *Vth, *Vtl, *AOh, *AOl;
    float* Vf;
    cudaGetSymbolAddress((void**)&qin_h, g_qin_h); cudaGetSymbolAddress((void**)&qin_l, g_qin_l);
    cudaGetSymbolAddress((void**)&kin_h, g_kin_h); cudaGetSymbolAddress((void**)&kin_l, g_kin_l);
    cudaGetSymbolAddress((void**)&vin_h, g_vin_h); cudaGetSymbolAddress((void**)&vin_l, g_vin_l);
    cudaGetSymbolAddress((void**)&wq_h, g_wq_h);   cudaGetSymbolAddress((void**)&wq_l, g_wq_l);
    cudaGetSymbolAddress((void**)&wk_h, g_wk_h);   cudaGetSymbolAddress((void**)&wk_l, g_wk_l);
    cudaGetSymbolAddress((void**)&wv_h, g_wv_h);   cudaGetSymbolAddress((void**)&wv_l, g_wv_l);
    cudaGetSymbolAddress((void**)&wo_h, g_wo_h);   cudaGetSymbolAddress((void**)&wo_l, g_wo_l);
    cudaGetSymbolAddress((void**)&Qh, g_Qh);       cudaGetSymbolAddress((void**)&Ql, g_Ql);
    cudaGetSymbolAddress((void**)&Kh, g_Kh);       cudaGetSymbolAddress((void**)&Kl, g_Kl);
    cudaGetSymbolAddress((void**)&Vf, g_Vf);
    cudaGetSymbolAddress((void**)&Vth, g_Vth);     cudaGetSymbolAddress((void**)&Vtl, g_Vtl);
    cudaGetSymbolAddress((void**)&AOh, g_AOh);     cudaGetSymbolAddress((void**)&AOl, g_AOl);

    const int NQ = NTOK * D_MODEL;     // 4M
    const int NW = D_MODEL * D_MODEL;  // 1M
    split_kernel<<<NQ / 1024, 256>>>(q, qin_h, qin_l, NQ);
    split_kernel<<<NQ / 1024, 256>>>(k, kin_h, kin_l, NQ);
    split_kernel<<<NQ / 1024, 256>>>(v, vin_h, vin_l, NQ);
    split_kernel<<<NW / 1024, 256>>>(Wq, wq_h, wq_l, NW);
    split_kernel<<<NW / 1024, 256>>>(Wk, wk_h, wk_l, NW);
    split_kernel<<<NW / 1024, 256>>>(Wv, wv_h, wv_l, NW);
    split_kernel<<<NW / 1024, 256>>>(Wo, wo_h, wo_l, NW);

    dim3 gp(D_MODEL / 128, NTOK / 128, 1);   // (8, 32)
    // Q projection (scale 1/sqrt(64) folded in) -> split
    mma_gemm<128, false, true><<<gp, 256>>>(qin_h, qin_l, D_MODEL, wq_h, wq_l, D_MODEL,
                                            D_MODEL / 32, 0.125f, nullptr, Qh, Ql, D_MODEL,
                                            0, 0, 0, 0, 0, 0);
    // K projection -> split
    mma_gemm<128, false, true><<<gp, 256>>>(kin_h, kin_l, D_MODEL, wk_h, wk_l, D_MODEL,
                                            D_MODEL / 32, 1.0f, nullptr, Kh, Kl, D_MODEL,
                                            0, 0, 0, 0, 0, 0);
    // V projection -> fp32
    mma_gemm<128, false, false><<<gp, 256>>>(vin_h, vin_l, D_MODEL, wv_h, wv_l, D_MODEL,
                                             D_MODEL / 32, 1.0f, Vf, nullptr, nullptr, D_MODEL,
                                             0, 0, 0, 0, 0, 0);
    // V transpose + split
    vtrans_kernel<<<dim3(SSEQ / 32, DKH / 32, BHN), dim3(32, 8)>>>(Vf, Vth, Vtl);

    // Scores = Qs @ K^T -> fp32 attnw (scale already folded into Q)
    dim3 gqk(SSEQ / 128, SSEQ / 128, BHN);   // (16, 16, 32)
    mma_gemm<128, false, false><<<gqk, 256>>>(Qh, Ql, D_MODEL, Kh, Kl, D_MODEL,
                                              DKH / 32, 1.0f, attnw, nullptr, nullptr, SSEQ,
                                              (size_t)SSEQ * D_MODEL, DKH,
                                              (size_t)SSEQ * D_MODEL, DKH,
                                              (size_t)NHEAD * SSEQ * SSEQ, (size_t)SSEQ * SSEQ);

    softmax_kernel<<<BHN * SSEQ, 256>>>(attnw);

    // attn_out = P @ Vt^T -> split AO
    dim3 gav(1, SSEQ / 128, BHN);            // (1, 16, 32)
    mma_gemm<64, true, true><<<gav, 256>>>(attnw, nullptr, SSEQ, Vth, Vtl, SSEQ,
                                           SSEQ / 32, 1.0f, nullptr, AOh, AOl, D_MODEL,
                                           (size_t)NHEAD * SSEQ * SSEQ, (size_t)SSEQ * SSEQ,
                                           (size_t)BHN / 2 * DKH * SSEQ, (size_t)DKH * SSEQ,
                                           (size_t)SSEQ * D_MODEL, DKH);

    // output = AO @ Wo^T -> fp32 d_out
    mma_gemm<128, false, false><<<gp, 256>>>(AOh, AOl, D_MODEL, wo_h, wo_l, D_MODEL,
                                             D_MODEL / 32, 1.0f, out, nullptr, nullptr, D_MODEL,
                                             0, 0, 0, 0, 0, 0);
}

// round 16
// speedup vs baseline: 2.0201x; 1.2056x over previous
#include <cuda_runtime.h>
#include <cuda_bf16.h>
#include <cstdint>

#define D_MODEL 1024
#define NHEAD   16
#define DKH     64
#define BB      2
#define SSEQ    2048
#define NTOK    (BB * SSEQ)      /* 4096 */
#define BHN     (BB * NHEAD)     /* 32   */

// ---------------------------------------------------------------------------
// PTX helpers: ldmatrix + mma.sync + cp.async (sm_80+, no arch-'a' features)
// ---------------------------------------------------------------------------
__device__ __forceinline__ uint32_t smem_u32(const void* p) {
    uint32_t a;
    asm("{ .reg .u64 t; cvta.to.shared.u64 t, %1; cvt.u32.u64 %0, t; }" : "=r"(a) : "l"(p));
    return a;
}

__device__ __forceinline__ void ldsm_x4(uint32_t* r, uint32_t addr) {
    asm volatile("ldmatrix.sync.aligned.m8n8.x4.shared.b16 {%0,%1,%2,%3}, [%4];"
                 : "=r"(r[0]), "=r"(r[1]), "=r"(r[2]), "=r"(r[3]) : "r"(addr));
}
__device__ __forceinline__ void ldsm_x2(uint32_t& r0, uint32_t& r1, uint32_t addr) {
    asm volatile("ldmatrix.sync.aligned.m8n8.x2.shared.b16 {%0,%1}, [%2];"
                 : "=r"(r0), "=r"(r1) : "r"(addr));
}
__device__ __forceinline__ void mma16816(float* c, const uint32_t* a, uint32_t b0, uint32_t b1) {
    asm volatile(
        "mma.sync.aligned.m16n8k16.row.col.f32.bf16.bf16.f32 "
        "{%0,%1,%2,%3}, {%4,%5,%6,%7}, {%8,%9}, {%0,%1,%2,%3};"
        : "+f"(c[0]), "+f"(c[1]), "+f"(c[2]), "+f"(c[3])
        : "r"(a[0]), "r"(a[1]), "r"(a[2]), "r"(a[3]), "r"(b0), "r"(b1));
}
__device__ __forceinline__ void cp_async16(uint32_t saddr, const void* gptr) {
    asm volatile("cp.async.cg.shared.global [%0], [%1], 16;" :: "r"(saddr), "l"(gptr));
}
#define CP_COMMIT()  asm volatile("cp.async.commit_group;" ::: "memory")
#define CP_WAIT(n)   asm volatile("cp.async.wait_group %0;" :: "n"(n) : "memory")

// ---------------------------------------------------------------------------
// Device scratch (bf16 hi/lo splits + fp32 V)
// ---------------------------------------------------------------------------
__device__ __nv_bfloat16 g_qin_h[NTOK * D_MODEL], g_qin_l[NTOK * D_MODEL];
__device__ __nv_bfloat16 g_kin_h[NTOK * D_MODEL], g_kin_l[NTOK * D_MODEL];
__device__ __nv_bfloat16 g_vin_h[NTOK * D_MODEL], g_vin_l[NTOK * D_MODEL];
__device__ __nv_bfloat16 g_wq_h[D_MODEL * D_MODEL], g_wq_l[D_MODEL * D_MODEL];
__device__ __nv_bfloat16 g_wk_h[D_MODEL * D_MODEL], g_wk_l[D_MODEL * D_MODEL];
__device__ __nv_bfloat16 g_wv_h[D_MODEL * D_MODEL], g_wv_l[D_MODEL * D_MODEL];
__device__ __nv_bfloat16 g_wo_h[D_MODEL * D_MODEL], g_wo_l[D_MODEL * D_MODEL];
__device__ __nv_bfloat16 g_Qh[NTOK * D_MODEL], g_Ql[NTOK * D_MODEL];
__device__ __nv_bfloat16 g_Kh[NTOK * D_MODEL], g_Kl[NTOK * D_MODEL];
__device__ float         g_Vf[NTOK * D_MODEL];
__device__ __nv_bfloat16 g_Vth[BHN * DKH * SSEQ], g_Vtl[BHN * DKH * SSEQ];
__device__ __nv_bfloat16 g_AOh[NTOK * D_MODEL], g_AOl[NTOK * D_MODEL];

// ---------------------------------------------------------------------------
// Elementwise split: x -> (hi, lo) bf16
// ---------------------------------------------------------------------------
__global__ __launch_bounds__(256)
void split_kernel(const float* __restrict__ x, __nv_bfloat16* __restrict__ h,
                  __nv_bfloat16* __restrict__ l, int n)
{
    int i = (blockIdx.x * 256 + threadIdx.x) * 4;
    if (i >= n) return;
    float4 v = *(const float4*)(x + i);
    __nv_bfloat16 h0 = __float2bfloat16(v.x), h1 = __float2bfloat16(v.y);
    __nv_bfloat16 h2 = __float2bfloat16(v.z), h3 = __float2bfloat16(v.w);
    __nv_bfloat16 l0 = __float2bfloat16(v.x - __bfloat162float(h0));
    __nv_bfloat16 l1 = __float2bfloat16(v.y - __bfloat162float(h1));
    __nv_bfloat16 l2 = __float2bfloat16(v.z - __bfloat162float(h2));
    __nv_bfloat16 l3 = __float2bfloat16(v.w - __bfloat162float(h3));
    __nv_bfloat162* hp = (__nv_bfloat162*)(h + i);
    hp[0] = __nv_bfloat162(h0, h1); hp[1] = __nv_bfloat162(h2, h3);
    __nv_bfloat162* lp = (__nv_bfloat162*)(l + i);
    lp[0] = __nv_bfloat162(l0, l1); lp[1] = __nv_bfloat162(l2, l3);
}

// ---------------------------------------------------------------------------
// V transpose + split: g_Vf[token][dmodel] -> Vt[bh][d][s] hi/lo
// ---------------------------------------------------------------------------
__global__ __launch_bounds__(256)
void vtrans_kernel(const float* __restrict__ V, __nv_bfloat16* __restrict__ Vh,
                   __nv_bfloat16* __restrict__ Vl)
{
    __shared__ float t[32][33];
    const int bh = blockIdx.z, b = bh >> 4, h = bh & 15;
    const int s0 = blockIdx.x * 32, d0 = blockIdx.y * 32;
    for (int i = threadIdx.y; i < 32; i += 8)
        t[i][threadIdx.x] = V[(size_t)(b * SSEQ + s0 + i) * D_MODEL + h * DKH + d0 + threadIdx.x];
    __syncthreads();
    for (int i = threadIdx.y; i < 32; i += 8) {
        float v = t[threadIdx.x][i];
        size_t o = (size_t)bh * DKH * SSEQ + (size_t)(d0 + i) * SSEQ + s0 + threadIdx.x;
        __nv_bfloat16 hh = __float2bfloat16(v);
        Vh[o] = hh;
        Vl[o] = __float2bfloat16(v - __bfloat162float(hh));
    }
}

// ---------------------------------------------------------------------------
// HMMA (mma.sync m16n8k16 bf16) GEMM.  M-tile=128, N-tile=NT, K-tile=32.
// C = alpha * (Ah+Al) @ (Bh+Bl)^T  via 3 accumulated MMA terms.
// !A_FP32: double-buffered cp.async pipeline (2 stages, dynamic smem).
// A_FP32:  A fp32 in gmem, split to hi/lo in SMEM on load (synchronous,
//          single stage) — AV kernel only.
// OUT_SPLIT: write Ch/Cl bf16 hi/lo; else fp32 Cf.
// 256 threads = 8 warps; NT=128: 2x4 warp grid; NT=64: 4x2 warp grid.
// ---------------------------------------------------------------------------
template<int NT, bool A_FP32, bool OUT_SPLIT>
__global__ __launch_bounds__(256)
void mma_gemm(const void* __restrict__ A0, const void* __restrict__ A1, size_t lda,
              const __nv_bfloat16* __restrict__ Bh, const __nv_bfloat16* __restrict__ Bl,
              size_t ldb, int kTiles, float alpha,
              float* __restrict__ Cf, __nv_bfloat16* __restrict__ Ch,
              __nv_bfloat16* __restrict__ Cl, size_t ldc,
              size_t aB, size_t aH, size_t bB, size_t bH, size_t cB, size_t cH)
{
    constexpr int KT = 32;                 // k per smem tile (bf16)
    constexpr int KS = KT + 8;             // padded row stride (elems), 80 B
    constexpr int WARPS_M = (NT == 128) ? 2 : 4;
    constexpr int WARPS_N = 8 / WARPS_M;
    constexpr int WTM = 128 / WARPS_M;     // 64 or 32
    constexpr int WTN = NT / WARPS_N;      // 32
    constexpr int MF = WTM / 16;           // 4 or 2
    constexpr int NF = WTN / 8;            // 4

    constexpr int A_BYTES = 128 * KS * 2;  // 10240
    constexpr int B_BYTES = NT * KS * 2;   // 10240 (NT=128) / 5120 (NT=64)
    constexpr int STAGE   = 2 * A_BYTES + 2 * B_BYTES;

    extern __shared__ __align__(16) char dyn[];
    const uint32_t sbase = smem_u32(dyn);

    const int tid = threadIdx.x;
    const int w = tid >> 5, lane = tid & 31;
    const int wm = w % WARPS_M, wn = w / WARPS_M;
    const int zb = blockIdx.z >> 4, zh = blockIdx.z & 15;
    const int m0 = blockIdx.y * 128, n0 = blockIdx.x * NT;

    const size_t aOff = (size_t)zb * aB + (size_t)zh * aH;
    const size_t bOff = (size_t)zb * bB + (size_t)zh * bH;
    const size_t cOff = (size_t)zb * cB + (size_t)zh * cH;

    const __nv_bfloat16* Bhp = Bh + bOff;
    const __nv_bfloat16* Blp = Bl + bOff;

    float acc[MF][NF][4];
#pragma unroll
    for (int i = 0; i < MF; i++)
#pragma unroll
        for (int j = 0; j < NF; j++)
#pragma unroll
            for (int e = 0; e < 4; e++) acc[i][j][e] = 0.f;

    // ldmatrix source offsets (fixed per thread)
    const int a_g = lane >> 3, a_r = lane & 7;
    const int a_row_off = (a_g & 1) * 8 + a_r;      // + mi*16 + wm*WTM
    const int a_col_off = (a_g >> 1) * 8;           // + k16
    const int b_row_off = lane & 7;                 // + ni*8 + wn*WTN
    const int b_col_off = ((lane >> 3) & 1) * 8;    // + k16

    if (!A_FP32) {
        // ================= pipelined path (2-stage cp.async) =================
        const __nv_bfloat16* Ahp = (const __nv_bfloat16*)A0 + aOff;
        const __nv_bfloat16* Alp = (const __nv_bfloat16*)A1 + aOff;

        auto issue_tile = [&](int kt, int st) {
            const uint32_t sAh = sbase + st * STAGE;
            const uint32_t sAl = sAh + A_BYTES;
            const uint32_t sBh = sAh + 2 * A_BYTES;
            const uint32_t sBl = sBh + B_BYTES;
#pragma unroll
            for (int it = 0; it < 2; it++) {
                int i = tid + it * 256;            // 512 uint4
                int r = i >> 2, c8 = (i & 3) * 8;
                uint32_t so = (uint32_t)(r * KS + c8) * 2;
                size_t g = (size_t)(m0 + r) * lda + (size_t)kt * KT + c8;
                cp_async16(sAh + so, Ahp + g);
                cp_async16(sAl + so, Alp + g);
            }
#pragma unroll
            for (int it = 0; it < NT / 64; it++) {
                int i = tid + it * 256;            // NT*4 uint4
                int r = i >> 2, c8 = (i & 3) * 8;
                uint32_t so = (uint32_t)(r * KS + c8) * 2;
                size_t g = (size_t)(n0 + r) * ldb + (size_t)kt * KT + c8;
                cp_async16(sBh + so, Bhp + g);
                cp_async16(sBl + so, Blp + g);
            }
        };

        issue_tile(0, 0);
        CP_COMMIT();

        for (int kt = 0; kt < kTiles; kt++) {
            const int st = kt & 1;
            if (kt + 1 < kTiles) {
                issue_tile(kt + 1, st ^ 1);
                CP_COMMIT();
                CP_WAIT(1);                       // group kt complete
            } else {
                CP_WAIT(0);
            }
            __syncthreads();

            const uint32_t uAh = sbase + st * STAGE;
            const uint32_t uAl = uAh + A_BYTES;
            const uint32_t uBh = uAh + 2 * A_BYTES;
            const uint32_t uBl = uBh + B_BYTES;
#pragma unroll
            for (int k16 = 0; k16 < KT; k16 += 16) {
                uint32_t aH[MF][4], aL[MF][4];
#pragma unroll
                for (int mi = 0; mi < MF; mi++) {
                    uint32_t off = (uint32_t)((wm * WTM + mi * 16 + a_row_off) * KS
                                              + k16 + a_col_off) * 2;
                    ldsm_x4(aH[mi], uAh + off);
                    ldsm_x4(aL[mi], uAl + off);
                }
#pragma unroll
                for (int ni = 0; ni < NF; ni++) {
                    uint32_t off = (uint32_t)((wn * WTN + ni * 8 + b_row_off) * KS
                                              + k16 + b_col_off) * 2;
                    uint32_t bh0, bh1, bl0, bl1;
                    ldsm_x2(bh0, bh1, uBh + off);
                    ldsm_x2(bl0, bl1, uBl + off);
#pragma unroll
                    for (int mi = 0; mi < MF; mi++) {
                        mma16816(acc[mi][ni], aH[mi], bh0, bh1);   // Ah*Bh
                        mma16816(acc[mi][ni], aH[mi], bl0, bl1);   // Ah*Bl
                        mma16816(acc[mi][ni], aL[mi], bh0, bh1);   // Al*Bh
                    }
                }
            }
            __syncthreads();                      // stage st free for kt+2
        }
    } else {
        // ================= synchronous path (fp32 A, AV kernel) ==============
        const float* Af = (const float*)A0 + aOff;
        const uint32_t uAh = sbase;
        const uint32_t uAl = uAh + A_BYTES;
        const uint32_t uBh = uAh + 2 * A_BYTES;
        const uint32_t uBl = uBh + B_BYTES;
        __nv_bfloat16* pAh = (__nv_bfloat16*)(dyn);
        __nv_bfloat16* pAl = (__nv_bfloat16*)(dyn + A_BYTES);
        __nv_bfloat16* pBh = (__nv_bfloat16*)(dyn + 2 * A_BYTES);
        __nv_bfloat16* pBl = (__nv_bfloat16*)(dyn + 2 * A_BYTES + B_BYTES);

        for (int kt = 0; kt < kTiles; kt++) {
#pragma unroll
            for (int it = 0; it < 4; it++) {
                int i = tid + it * 256;            // 1024 float4
                int r = i >> 3, c4 = (i & 7) * 4;
                float4 v = *(const float4*)(Af + (size_t)(m0 + r) * lda + (size_t)kt * KT + c4);
                __nv_bfloat16 h0 = __float2bfloat16(v.x), h1 = __float2bfloat16(v.y);
                __nv_bfloat16 h2 = __float2bfloat16(v.z), h3 = __float2bfloat16(v.w);
                __nv_bfloat16 l0 = __float2bfloat16(v.x - __bfloat162float(h0));
                __nv_bfloat16 l1 = __float2bfloat16(v.y - __bfloat162float(h1));
                __nv_bfloat16 l2 = __float2bfloat16(v.z - __bfloat162float(h2));
                __nv_bfloat16 l3 = __float2bfloat16(v.w - __bfloat162float(h3));
                uint2 hp, lp;
                __nv_bfloat162 t0(h0, h1), t1(h2, h3);
                hp.x = *(uint32_t*)&t0; hp.y = *(uint32_t*)&t1;
                __nv_bfloat162 t2(l0, l1), t3(l2, l3);
                lp.x = *(uint32_t*)&t2; lp.y = *(uint32_t*)&t3;
                *(uint2*)&pAh[r * KS + c4] = hp;
                *(uint2*)&pAl[r * KS + c4] = lp;
            }
#pragma unroll
            for (int it = 0; it < NT / 64; it++) {
                int i = tid + it * 256;
                int r = i >> 2, c8 = (i & 3) * 8;
                size_t g = (size_t)(n0 + r) * ldb + (size_t)kt * KT + c8;
                *(uint4*)&pBh[r * KS + c8] = *(const uint4*)(Bhp + g);
                *(uint4*)&pBl[r * KS + c8] = *(const uint4*)(Blp + g);
            }
            __syncthreads();

#pragma unroll
            for (int k16 = 0; k16 < KT; k16 += 16) {
                uint32_t aH[MF][4], aL[MF][4];
#pragma unroll
                for (int mi = 0; mi < MF; mi++) {
                    uint32_t off = (uint32_t)((wm * WTM + mi * 16 + a_row_off) * KS
                                              + k16 + a_col_off) * 2;
                    ldsm_x4(aH[mi], uAh + off);
                    ldsm_x4(aL[mi], uAl + off);
                }
#pragma unroll
                for (int ni = 0; ni < NF; ni++) {
                    uint32_t off = (uint32_t)((wn * WTN + ni * 8 + b_row_off) * KS
                                              + k16 + b_col_off) * 2;
                    uint32_t bh0, bh1, bl0, bl1;
                    ldsm_x2(bh0, bh1, uBh + off);
                    ldsm_x2(bl0, bl1, uBl + off);
#pragma unroll
                    for (int mi = 0; mi < MF; mi++) {
                        mma16816(acc[mi][ni], aH[mi], bh0, bh1);
                        mma16816(acc[mi][ni], aH[mi], bl0, bl1);
                        mma16816(acc[mi][ni], aL[mi], bh0, bh1);
                    }
                }
            }
            __syncthreads();
        }
    }

    // ---- epilogue: fragment -> gmem ----
    const int er = lane >> 2, ec = (lane & 3) * 2;
#pragma unroll
    for (int mi = 0; mi < MF; mi++) {
#pragma unroll
        for (int ni = 0; ni < NF; ni++) {
            int row = m0 + wm * WTM + mi * 16 + er;
            int col = n0 + wn * WTN + ni * 8 + ec;
#pragma unroll
            for (int half = 0; half < 2; half++) {
                float v0 = alpha * acc[mi][ni][half * 2 + 0];
                float v1 = alpha * acc[mi][ni][half * 2 + 1];
                size_t off = cOff + (size_t)(row + half * 8) * ldc + col;
                if (OUT_SPLIT) {
                    __nv_bfloat16 h0 = __float2bfloat16(v0);
                    __nv_bfloat16 h1 = __float2bfloat16(v1);
                    __nv_bfloat16 l0 = __float2bfloat16(v0 - __bfloat162float(h0));
                    __nv_bfloat16 l1 = __float2bfloat16(v1 - __bfloat162float(h1));
                    __nv_bfloat162 hp(h0, h1), lp(l0, l1);
                    *(__nv_bfloat162*)(Ch + off) = hp;
                    *(__nv_bfloat162*)(Cl + off) = lp;
                } else {
                    *(float2*)(Cf + off) = make_float2(v0, v1);
                }
            }
        }
    }
}

// ---------------------------------------------------------------------------
// In-place row softmax (unchanged from passing baseline)
// ---------------------------------------------------------------------------
__global__ __launch_bounds__(256)
void softmax_kernel(float* __restrict__ P)
{
    float* p = P + (size_t)blockIdx.x * SSEQ;
    const int tid = threadIdx.x;
    __shared__ float sbuf[8];
    __shared__ float sres;

    float v[8];
    float m = -3.402823e38f;
#pragma unroll
    for (int i = 0; i < 8; i++) { v[i] = p[tid + i * 256]; m = fmaxf(m, v[i]); }
#pragma unroll
    for (int o = 16; o > 0; o >>= 1) m = fmaxf(m, __shfl_xor_sync(0xffffffffu, m, o));
    if ((tid & 31) == 0) sbuf[tid >> 5] = m;
    __syncthreads();
    if (tid == 0) {
        float mm = sbuf[0];
#pragma unroll
        for (int w = 1; w < 8; w++) mm = fmaxf(mm, sbuf[w]);
        sres = mm;
    }
    __syncthreads();
    m = sres;

    float l = 0.f;
#pragma unroll
    for (int i = 0; i < 8; i++) { v[i] = __expf(v[i] - m); l += v[i]; }
#pragma unroll
    for (int o = 16; o > 0; o >>= 1) l += __shfl_xor_sync(0xffffffffu, l, o);
    __syncthreads();
    if ((tid & 31) == 0) sbuf[tid >> 5] = l;
    __syncthreads();
    if (tid == 0) {
        float ll = 0.f;
#pragma unroll
        for (int w = 0; w < 8; w++) ll += sbuf[w];
        sres = 1.f / ll;
    }
    __syncthreads();
    const float inv = sres;
#pragma unroll
    for (int i = 0; i < 8; i++) p[tid + i * 256] = v[i] * inv;
}

// ---------------------------------------------------------------------------
extern "C" void kernel_launch(void* const* d_in, const int* in_sizes, int n_in,
                              void* d_out, int out_size)
{
    const float* q  = (const float*)d_in[0];
    const float* k  = (const float*)d_in[1];
    const float* v  = (const float*)d_in[2];
    const float* Wq = (const float*)d_in[3];
    const float* Wk = (const float*)d_in[4];
    const float* Wv = (const float*)d_in[5];
    const float* Wo = (const float*)d_in[6];

    float* out   = (float*)d_out;
    float* attnw = out + (size_t)NTOK * D_MODEL;

    __nv_bfloat16 *qin_h, *qin_l, *kin_h, *kin_l, *vin_h, *vin_l;
    __nv_bfloat16 *wq_h, *wq_l, *wk_h, *wk_l, *wv_h, *wv_l, *wo_h, *wo_l;
    __nv_bfloat16 *Qh, *Ql, *Kh, *Kl, *Vth, *Vtl, *AOh, *AOl;
    float* Vf;
    cudaGetSymbolAddress((void**)&qin_h, g_qin_h); cudaGetSymbolAddress((void**)&qin_l, g_qin_l);
    cudaGetSymbolAddress((void**)&kin_h, g_kin_h); cudaGetSymbolAddress((void**)&kin_l, g_kin_l);
    cudaGetSymbolAddress((void**)&vin_h, g_vin_h); cudaGetSymbolAddress((void**)&vin_l, g_vin_l);
    cudaGetSymbolAddress((void**)&wq_h, g_wq_h);   cudaGetSymbolAddress((void**)&wq_l, g_wq_l);
    cudaGetSymbolAddress((void**)&wk_h, g_wk_h);   cudaGetSymbolAddress((void**)&wk_l, g_wk_l);
    cudaGetSymbolAddress((void**)&wv_h, g_wv_h);   cudaGetSymbolAddress((void**)&wv_l, g_wv_l);
    cudaGetSymbolAddress((void**)&wo_h, g_wo_h);   cudaGetSymbolAddress((void**)&wo_l, g_wo_l);
    cudaGetSymbolAddress((void**)&Qh, g_Qh);       cudaGetSymbolAddress((void**)&Ql, g_Ql);
    cudaGetSymbolAddress((void**)&Kh, g_Kh);       cudaGetSymbolAddress((void**)&Kl, g_Kl);
    cudaGetSymbolAddress((void**)&Vf, g_Vf);
    cudaGetSymbolAddress((void**)&Vth, g_Vth);     cudaGetSymbolAddress((void**)&Vtl, g_Vtl);
    cudaGetSymbolAddress((void**)&AOh, g_AOh);     cudaGetSymbolAddress((void**)&AOl, g_AOl);

    // dynamic smem sizes
    const int KS = 40;
    const int SM_PIPE = 2 * (2 * 128 * KS * 2 + 2 * 128 * KS * 2);   // 81920
    const int SM_AV   = 2 * 128 * KS * 2 + 2 * 64 * KS * 2;          // 30720

    auto* kProjSplit = mma_gemm<128, false, true>;
    auto* kProjF32   = mma_gemm<128, false, false>;
    auto* kAV        = mma_gemm<64, true, true>;
    cudaFuncSetAttribute(kProjSplit, cudaFuncAttributeMaxDynamicSharedMemorySize, SM_PIPE);
    cudaFuncSetAttribute(kProjF32,   cudaFuncAttributeMaxDynamicSharedMemorySize, SM_PIPE);
    cudaFuncSetAttribute(kAV,        cudaFuncAttributeMaxDynamicSharedMemorySize, SM_AV);

    const int NQ = NTOK * D_MODEL;     // 4M
    const int NW = D_MODEL * D_MODEL;  // 1M
    split_kernel<<<NQ / 1024, 256>>>(q, qin_h, qin_l, NQ);
    split_kernel<<<NQ / 1024, 256>>>(k, kin_h, kin_l, NQ);
    split_kernel<<<NQ / 1024, 256>>>(v, vin_h, vin_l, NQ);
    split_kernel<<<NW / 1024, 256>>>(Wq, wq_h, wq_l, NW);
    split_kernel<<<NW / 1024, 256>>>(Wk, wk_h, wk_l, NW);
    split_kernel<<<NW / 1024, 256>>>(Wv, wv_h, wv_l, NW);
    split_kernel<<<NW / 1024, 256>>>(Wo, wo_h, wo_l, NW);

    dim3 gp(D_MODEL / 128, NTOK / 128, 1);   // (8, 32)
    // Q projection (scale 1/sqrt(64) folded in) -> split
    kProjSplit<<<gp, 256, SM_PIPE>>>(qin_h, qin_l, D_MODEL, wq_h, wq_l, D_MODEL,
                                     D_MODEL / 32, 0.125f, nullptr, Qh, Ql, D_MODEL,
                                     0, 0, 0, 0, 0, 0);
    // K projection -> split
    kProjSplit<<<gp, 256, SM_PIPE>>>(kin_h, kin_l, D_MODEL, wk_h, wk_l, D_MODEL,
                                     D_MODEL / 32, 1.0f, nullptr, Kh, Kl, D_MODEL,
                                     0, 0, 0, 0, 0, 0);
    // V projection -> fp32
    kProjF32<<<gp, 256, SM_PIPE>>>(vin_h, vin_l, D_MODEL, wv_h, wv_l, D_MODEL,
                                   D_MODEL / 32, 1.0f, Vf, nullptr, nullptr, D_MODEL,
                                   0, 0, 0, 0, 0, 0);
    // V transpose + split
    vtrans_kernel<<<dim3(SSEQ / 32, DKH / 32, BHN), dim3(32, 8)>>>(Vf, Vth, Vtl);

    // Scores = Qs @ K^T -> fp32 attnw (scale already folded into Q)
    dim3 gqk(SSEQ / 128, SSEQ / 128, BHN);   // (16, 16, 32)
    kProjF32<<<gqk, 256, SM_PIPE>>>(Qh, Ql, D_MODEL, Kh, Kl, D_MODEL,
                                    DKH / 32, 1.0f, attnw, nullptr, nullptr, SSEQ,
                                    (size_t)SSEQ * D_MODEL, DKH,
                                    (size_t)SSEQ * D_MODEL, DKH,
                                    (size_t)NHEAD * SSEQ * SSEQ, (size_t)SSEQ * SSEQ);

    softmax_kernel<<<BHN * SSEQ, 256>>>(attnw);

    // attn_out = P @ Vt^T -> split AO
    dim3 gav(1, SSEQ / 128, BHN);            // (1, 16, 32)
    kAV<<<gav, 256, SM_AV>>>(attnw, nullptr, SSEQ, Vth, Vtl, SSEQ,
                             SSEQ / 32, 1.0f, nullptr, AOh, AOl, D_MODEL,
                             (size_t)NHEAD * SSEQ * SSEQ, (size_t)SSEQ * SSEQ,
                             (size_t)BHN / 2 * DKH * SSEQ, (size_t)DKH * SSEQ,
                             (size_t)SSEQ * D_MODEL, DKH);

    // output = AO @ Wo^T -> fp32 d_out
    kProjF32<<<gp, 256, SM_PIPE>>>(AOh, AOl, D_MODEL, wo_h, wo_l, D_MODEL,
                                   D_MODEL / 32, 1.0f, out, nullptr, nullptr, D_MODEL,
                                   0, 0, 0, 0, 0, 0);
}

// round 17
// speedup vs baseline: 2.0433x; 1.0115x over previous
#include <cuda_runtime.h>
#include <cuda_bf16.h>
#include <cstdint>

#define D_MODEL 1024
#define NHEAD   16
#define DKH     64
#define BB      2
#define SSEQ    2048
#define NTOK    (BB * SSEQ)      /* 4096 */
#define BHN     (BB * NHEAD)     /* 32   */

// ---------------------------------------------------------------------------
// PTX helpers: ldmatrix + mma.sync + cp.async (sm_80+, no arch-'a' features)
// ---------------------------------------------------------------------------
__device__ __forceinline__ uint32_t smem_u32(const void* p) {
    uint32_t a;
    asm("{ .reg .u64 t; cvta.to.shared.u64 t, %1; cvt.u32.u64 %0, t; }" : "=r"(a) : "l"(p));
    return a;
}

__device__ __forceinline__ void ldsm_x4(uint32_t* r, uint32_t addr) {
    asm volatile("ldmatrix.sync.aligned.m8n8.x4.shared.b16 {%0,%1,%2,%3}, [%4];"
                 : "=r"(r[0]), "=r"(r[1]), "=r"(r[2]), "=r"(r[3]) : "r"(addr));
}
__device__ __forceinline__ void ldsm_x2(uint32_t& r0, uint32_t& r1, uint32_t addr) {
    asm volatile("ldmatrix.sync.aligned.m8n8.x2.shared.b16 {%0,%1}, [%2];"
                 : "=r"(r0), "=r"(r1) : "r"(addr));
}
__device__ __forceinline__ void mma16816(float* c, const uint32_t* a, uint32_t b0, uint32_t b1) {
    asm volatile(
        "mma.sync.aligned.m16n8k16.row.col.f32.bf16.bf16.f32 "
        "{%0,%1,%2,%3}, {%4,%5,%6,%7}, {%8,%9}, {%0,%1,%2,%3};"
        : "+f"(c[0]), "+f"(c[1]), "+f"(c[2]), "+f"(c[3])
        : "r"(a[0]), "r"(a[1]), "r"(a[2]), "r"(a[3]), "r"(b0), "r"(b1));
}
__device__ __forceinline__ void cp_async16(uint32_t saddr, const void* gptr) {
    asm volatile("cp.async.cg.shared.global [%0], [%1], 16;" :: "r"(saddr), "l"(gptr));
}
#define CP_COMMIT()  asm volatile("cp.async.commit_group;" ::: "memory")
#define CP_WAIT(n)   asm volatile("cp.async.wait_group %0;" :: "n"(n) : "memory")

// ---------------------------------------------------------------------------
// Device scratch (bf16 hi/lo splits + fp32 V + P splits)
// ---------------------------------------------------------------------------
__device__ __nv_bfloat16 g_qin_h[NTOK * D_MODEL], g_qin_l[NTOK * D_MODEL];
__device__ __nv_bfloat16 g_kin_h[NTOK * D_MODEL], g_kin_l[NTOK * D_MODEL];
__device__ __nv_bfloat16 g_vin_h[NTOK * D_MODEL], g_vin_l[NTOK * D_MODEL];
__device__ __nv_bfloat16 g_wq_h[D_MODEL * D_MODEL], g_wq_l[D_MODEL * D_MODEL];
__device__ __nv_bfloat16 g_wk_h[D_MODEL * D_MODEL], g_wk_l[D_MODEL * D_MODEL];
__device__ __nv_bfloat16 g_wv_h[D_MODEL * D_MODEL], g_wv_l[D_MODEL * D_MODEL];
__device__ __nv_bfloat16 g_wo_h[D_MODEL * D_MODEL], g_wo_l[D_MODEL * D_MODEL];
__device__ __nv_bfloat16 g_Qh[NTOK * D_MODEL], g_Ql[NTOK * D_MODEL];
__device__ __nv_bfloat16 g_Kh[NTOK * D_MODEL], g_Kl[NTOK * D_MODEL];
__device__ float         g_Vf[NTOK * D_MODEL];
__device__ __nv_bfloat16 g_Vth[BHN * DKH * SSEQ], g_Vtl[BHN * DKH * SSEQ];
__device__ __nv_bfloat16 g_AOh[NTOK * D_MODEL], g_AOl[NTOK * D_MODEL];
__device__ __nv_bfloat16 g_Ph[(size_t)BHN * SSEQ * SSEQ];
__device__ __nv_bfloat16 g_Pl[(size_t)BHN * SSEQ * SSEQ];

// ---------------------------------------------------------------------------
// Elementwise split: x -> (hi, lo) bf16
// ---------------------------------------------------------------------------
__global__ __launch_bounds__(256)
void split_kernel(const float* __restrict__ x, __nv_bfloat16* __restrict__ h,
                  __nv_bfloat16* __restrict__ l, int n)
{
    int i = (blockIdx.x * 256 + threadIdx.x) * 4;
    if (i >= n) return;
    float4 v = *(const float4*)(x + i);
    __nv_bfloat16 h0 = __float2bfloat16(v.x), h1 = __float2bfloat16(v.y);
    __nv_bfloat16 h2 = __float2bfloat16(v.z), h3 = __float2bfloat16(v.w);
    __nv_bfloat16 l0 = __float2bfloat16(v.x - __bfloat162float(h0));
    __nv_bfloat16 l1 = __float2bfloat16(v.y - __bfloat162float(h1));
    __nv_bfloat16 l2 = __float2bfloat16(v.z - __bfloat162float(h2));
    __nv_bfloat16 l3 = __float2bfloat16(v.w - __bfloat162float(h3));
    __nv_bfloat162* hp = (__nv_bfloat162*)(h + i);
    hp[0] = __nv_bfloat162(h0, h1); hp[1] = __nv_bfloat162(h2, h3);
    __nv_bfloat162* lp = (__nv_bfloat162*)(l + i);
    lp[0] = __nv_bfloat162(l0, l1); lp[1] = __nv_bfloat162(l2, l3);
}

// ---------------------------------------------------------------------------
// V transpose + split: g_Vf[token][dmodel] -> Vt[bh][d][s] hi/lo
// ---------------------------------------------------------------------------
__global__ __launch_bounds__(256)
void vtrans_kernel(const float* __restrict__ V, __nv_bfloat16* __restrict__ Vh,
                   __nv_bfloat16* __restrict__ Vl)
{
    __shared__ float t[32][33];
    const int bh = blockIdx.z, b = bh >> 4, h = bh & 15;
    const int s0 = blockIdx.x * 32, d0 = blockIdx.y * 32;
    for (int i = threadIdx.y; i < 32; i += 8)
        t[i][threadIdx.x] = V[(size_t)(b * SSEQ + s0 + i) * D_MODEL + h * DKH + d0 + threadIdx.x];
    __syncthreads();
    for (int i = threadIdx.y; i < 32; i += 8) {
        float v = t[threadIdx.x][i];
        size_t o = (size_t)bh * DKH * SSEQ + (size_t)(d0 + i) * SSEQ + s0 + threadIdx.x;
        __nv_bfloat16 hh = __float2bfloat16(v);
        Vh[o] = hh;
        Vl[o] = __float2bfloat16(v - __bfloat162float(hh));
    }
}

// ---------------------------------------------------------------------------
// HMMA (mma.sync m16n8k16 bf16) GEMM.  M-tile=128, N-tile=NT, K-tile=32.
// C = alpha * (Ah+Al) @ (Bh+Bl)^T  via 3 accumulated MMA terms.
// 2-stage cp.async pipeline (dynamic smem). All operands bf16 hi/lo.
// OUT_SPLIT: write Ch/Cl bf16 hi/lo; else fp32 Cf.
// 256 threads = 8 warps; NT=128: 2x4 warp grid; NT=64: 4x2 warp grid.
// ---------------------------------------------------------------------------
template<int NT, bool OUT_SPLIT>
__global__ __launch_bounds__(256)
void mma_gemm(const __nv_bfloat16* __restrict__ Ah, const __nv_bfloat16* __restrict__ Al,
              size_t lda,
              const __nv_bfloat16* __restrict__ Bh, const __nv_bfloat16* __restrict__ Bl,
              size_t ldb, int kTiles, float alpha,
              float* __restrict__ Cf, __nv_bfloat16* __restrict__ Ch,
              __nv_bfloat16* __restrict__ Cl, size_t ldc,
              size_t aB, size_t aH, size_t bB, size_t bH, size_t cB, size_t cH)
{
    constexpr int KT = 32;                 // k per smem tile (bf16)
    constexpr int KS = KT + 8;             // padded row stride (elems), 80 B
    constexpr int WARPS_M = (NT == 128) ? 2 : 4;
    constexpr int WARPS_N = 8 / WARPS_M;
    constexpr int WTM = 128 / WARPS_M;     // 64 or 32
    constexpr int WTN = NT / WARPS_N;      // 32
    constexpr int MF = WTM / 16;           // 4 or 2
    constexpr int NF = WTN / 8;            // 4

    constexpr int A_BYTES = 128 * KS * 2;  // 10240
    constexpr int B_BYTES = NT * KS * 2;   // 10240 (NT=128) / 5120 (NT=64)
    constexpr int STAGE   = 2 * A_BYTES + 2 * B_BYTES;

    extern __shared__ __align__(16) char dyn[];
    const uint32_t sbase = smem_u32(dyn);

    const int tid = threadIdx.x;
    const int w = tid >> 5, lane = tid & 31;
    const int wm = w % WARPS_M, wn = w / WARPS_M;
    const int zb = blockIdx.z >> 4, zh = blockIdx.z & 15;
    const int m0 = blockIdx.y * 128, n0 = blockIdx.x * NT;

    const size_t aOff = (size_t)zb * aB + (size_t)zh * aH;
    const size_t bOff = (size_t)zb * bB + (size_t)zh * bH;
    const size_t cOff = (size_t)zb * cB + (size_t)zh * cH;

    const __nv_bfloat16* Ahp = Ah + aOff;
    const __nv_bfloat16* Alp = Al + aOff;
    const __nv_bfloat16* Bhp = Bh + bOff;
    const __nv_bfloat16* Blp = Bl + bOff;

    float acc[MF][NF][4];
#pragma unroll
    for (int i = 0; i < MF; i++)
#pragma unroll
        for (int j = 0; j < NF; j++)
#pragma unroll
            for (int e = 0; e < 4; e++) acc[i][j][e] = 0.f;

    // ldmatrix source offsets (fixed per thread)
    const int a_g = lane >> 3, a_r = lane & 7;
    const int a_row_off = (a_g & 1) * 8 + a_r;      // + mi*16 + wm*WTM
    const int a_col_off = (a_g >> 1) * 8;           // + k16
    const int b_row_off = lane & 7;                 // + ni*8 + wn*WTN
    const int b_col_off = ((lane >> 3) & 1) * 8;    // + k16

    auto issue_tile = [&](int kt, int st) {
        const uint32_t sAh = sbase + st * STAGE;
        const uint32_t sAl = sAh + A_BYTES;
        const uint32_t sBh = sAh + 2 * A_BYTES;
        const uint32_t sBl = sBh + B_BYTES;
#pragma unroll
        for (int it = 0; it < 2; it++) {
            int i = tid + it * 256;            // 512 uint4
            int r = i >> 2, c8 = (i & 3) * 8;
            uint32_t so = (uint32_t)(r * KS + c8) * 2;
            size_t g = (size_t)(m0 + r) * lda + (size_t)kt * KT + c8;
            cp_async16(sAh + so, Ahp + g);
            cp_async16(sAl + so, Alp + g);
        }
#pragma unroll
        for (int it = 0; it < NT / 64; it++) {
            int i = tid + it * 256;            // NT*4 uint4
            int r = i >> 2, c8 = (i & 3) * 8;
            uint32_t so = (uint32_t)(r * KS + c8) * 2;
            size_t g = (size_t)(n0 + r) * ldb + (size_t)kt * KT + c8;
            cp_async16(sBh + so, Bhp + g);
            cp_async16(sBl + so, Blp + g);
        }
    };

    issue_tile(0, 0);
    CP_COMMIT();

    for (int kt = 0; kt < kTiles; kt++) {
        const int st = kt & 1;
        if (kt + 1 < kTiles) {
            issue_tile(kt + 1, st ^ 1);
            CP_COMMIT();
            CP_WAIT(1);                       // group kt complete
        } else {
            CP_WAIT(0);
        }
        __syncthreads();

        const uint32_t uAh = sbase + st * STAGE;
        const uint32_t uAl = uAh + A_BYTES;
        const uint32_t uBh = uAh + 2 * A_BYTES;
        const uint32_t uBl = uBh + B_BYTES;
#pragma unroll
        for (int k16 = 0; k16 < KT; k16 += 16) {
            uint32_t aH[MF][4], aL[MF][4];
#pragma unroll
            for (int mi = 0; mi < MF; mi++) {
                uint32_t off = (uint32_t)((wm * WTM + mi * 16 + a_row_off) * KS
                                          + k16 + a_col_off) * 2;
                ldsm_x4(aH[mi], uAh + off);
                ldsm_x4(aL[mi], uAl + off);
            }
#pragma unroll
            for (int ni = 0; ni < NF; ni++) {
                uint32_t off = (uint32_t)((wn * WTN + ni * 8 + b_row_off) * KS
                                          + k16 + b_col_off) * 2;
                uint32_t bh0, bh1, bl0, bl1;
                ldsm_x2(bh0, bh1, uBh + off);
                ldsm_x2(bl0, bl1, uBl + off);
#pragma unroll
                for (int mi = 0; mi < MF; mi++) {
                    mma16816(acc[mi][ni], aH[mi], bh0, bh1);   // Ah*Bh
                    mma16816(acc[mi][ni], aH[mi], bl0, bl1);   // Ah*Bl
                    mma16816(acc[mi][ni], aL[mi], bh0, bh1);   // Al*Bh
                }
            }
        }
        __syncthreads();                      // stage st free for kt+2
    }

    // ---- epilogue: fragment -> gmem ----
    const int er = lane >> 2, ec = (lane & 3) * 2;
#pragma unroll
    for (int mi = 0; mi < MF; mi++) {
#pragma unroll
        for (int ni = 0; ni < NF; ni++) {
            int row = m0 + wm * WTM + mi * 16 + er;
            int col = n0 + wn * WTN + ni * 8 + ec;
#pragma unroll
            for (int half = 0; half < 2; half++) {
                float v0 = alpha * acc[mi][ni][half * 2 + 0];
                float v1 = alpha * acc[mi][ni][half * 2 + 1];
                size_t off = cOff + (size_t)(row + half * 8) * ldc + col;
                if (OUT_SPLIT) {
                    __nv_bfloat16 h0 = __float2bfloat16(v0);
                    __nv_bfloat16 h1 = __float2bfloat16(v1);
                    __nv_bfloat16 l0 = __float2bfloat16(v0 - __bfloat162float(h0));
                    __nv_bfloat16 l1 = __float2bfloat16(v1 - __bfloat162float(h1));
                    __nv_bfloat162 hp(h0, h1), lp(l0, l1);
                    *(__nv_bfloat162*)(Ch + off) = hp;
                    *(__nv_bfloat162*)(Cl + off) = lp;
                } else {
                    *(float2*)(Cf + off) = make_float2(v0, v1);
                }
            }
        }
    }
}

// ---------------------------------------------------------------------------
// In-place row softmax + P hi/lo split (fused; numerics identical to the
// previous AV in-kernel conversion).
// ---------------------------------------------------------------------------
__global__ __launch_bounds__(256)
void softmax_kernel(float* __restrict__ P, __nv_bfloat16* __restrict__ Ph,
                    __nv_bfloat16* __restrict__ Pl)
{
    const size_t base = (size_t)blockIdx.x * SSEQ;
    float* p = P + base;
    const int tid = threadIdx.x;
    __shared__ float sbuf[8];
    __shared__ float sres;

    float v[8];
    float m = -3.402823e38f;
#pragma unroll
    for (int i = 0; i < 8; i++) { v[i] = p[tid + i * 256]; m = fmaxf(m, v[i]); }
#pragma unroll
    for (int o = 16; o > 0; o >>= 1) m = fmaxf(m, __shfl_xor_sync(0xffffffffu, m, o));
    if ((tid & 31) == 0) sbuf[tid >> 5] = m;
    __syncthreads();
    if (tid == 0) {
        float mm = sbuf[0];
#pragma unroll
        for (int w = 1; w < 8; w++) mm = fmaxf(mm, sbuf[w]);
        sres = mm;
    }
    __syncthreads();
    m = sres;

    float l = 0.f;
#pragma unroll
    for (int i = 0; i < 8; i++) { v[i] = __expf(v[i] - m); l += v[i]; }
#pragma unroll
    for (int o = 16; o > 0; o >>= 1) l += __shfl_xor_sync(0xffffffffu, l, o);
    __syncthreads();
    if ((tid & 31) == 0) sbuf[tid >> 5] = l;
    __syncthreads();
    if (tid == 0) {
        float ll = 0.f;
#pragma unroll
        for (int w = 0; w < 8; w++) ll += sbuf[w];
        sres = 1.f / ll;
    }
    __syncthreads();
    const float inv = sres;
#pragma unroll
    for (int i = 0; i < 8; i++) {
        float pv = v[i] * inv;
        p[tid + i * 256] = pv;
        __nv_bfloat16 hh = __float2bfloat16(pv);
        Ph[base + tid + i * 256] = hh;
        Pl[base + tid + i * 256] = __float2bfloat16(pv - __bfloat162float(hh));
    }
}

// ---------------------------------------------------------------------------
extern "C" void kernel_launch(void* const* d_in, const int* in_sizes, int n_in,
                              void* d_out, int out_size)
{
    const float* q  = (const float*)d_in[0];
    const float* k  = (const float*)d_in[1];
    const float* v  = (const float*)d_in[2];
    const float* Wq = (const float*)d_in[3];
    const float* Wk = (const float*)d_in[4];
    const float* Wv = (const float*)d_in[5];
    const float* Wo = (const float*)d_in[6];

    float* out   = (float*)d_out;
    float* attnw = out + (size_t)NTOK * D_MODEL;

    __nv_bfloat16 *qin_h, *qin_l, *kin_h, *kin_l, *vin_h, *vin_l;
    __nv_bfloat16 *wq_h, *wq_l, *wk_h, *wk_l, *wv_h, *wv_l, *wo_h, *wo_l;
    __nv_bfloat16 *Qh, *Ql, *Kh, *Kl, *Vth, *Vtl, *AOh, *AOl, *Ph, *Pl;
    float* Vf;
    cudaGetSymbolAddress((void**)&qin_h, g_qin_h); cudaGetSymbolAddress((void**)&qin_l, g_qin_l);
    cudaGetSymbolAddress((void**)&kin_h, g_kin_h); cudaGetSymbolAddress((void**)&kin_l, g_kin_l);
    cudaGetSymbolAddress((void**)&vin_h, g_vin_h); cudaGetSymbolAddress((void**)&vin_l, g_vin_l);
    cudaGetSymbolAddress((void**)&wq_h, g_wq_h);   cudaGetSymbolAddress((void**)&wq_l, g_wq_l);
    cudaGetSymbolAddress((void**)&wk_h, g_wk_h);   cudaGetSymbolAddress((void**)&wk_l, g_wk_l);
    cudaGetSymbolAddress((void**)&wv_h, g_wv_h);   cudaGetSymbolAddress((void**)&wv_l, g_wv_l);
    cudaGetSymbolAddress((void**)&wo_h, g_wo_h);   cudaGetSymbolAddress((void**)&wo_l, g_wo_l);
    cudaGetSymbolAddress((void**)&Qh, g_Qh);       cudaGetSymbolAddress((void**)&Ql, g_Ql);
    cudaGetSymbolAddress((void**)&Kh, g_Kh);       cudaGetSymbolAddress((void**)&Kl, g_Kl);
    cudaGetSymbolAddress((void**)&Vf, g_Vf);
    cudaGetSymbolAddress((void**)&Vth, g_Vth);     cudaGetSymbolAddress((void**)&Vtl, g_Vtl);
    cudaGetSymbolAddress((void**)&AOh, g_AOh);     cudaGetSymbolAddress((void**)&AOl, g_AOl);
    cudaGetSymbolAddress((void**)&Ph, g_Ph);       cudaGetSymbolAddress((void**)&Pl, g_Pl);

    // dynamic smem sizes
    const int KS = 40;
    const int SM_PIPE = 2 * (2 * 128 * KS * 2 + 2 * 128 * KS * 2);   // 81920
    const int SM_AV   = 2 * (2 * 128 * KS * 2 + 2 * 64 * KS * 2);    // 61440

    auto* kProjSplit = mma_gemm<128, true>;
    auto* kProjF32   = mma_gemm<128, false>;
    auto* kAV        = mma_gemm<64, true>;
    cudaFuncSetAttribute(kProjSplit, cudaFuncAttributeMaxDynamicSharedMemorySize, SM_PIPE);
    cudaFuncSetAttribute(kProjF32,   cudaFuncAttributeMaxDynamicSharedMemorySize, SM_PIPE);
    cudaFuncSetAttribute(kAV,        cudaFuncAttributeMaxDynamicSharedMemorySize, SM_AV);

    const int NQ = NTOK * D_MODEL;     // 4M
    const int NW = D_MODEL * D_MODEL;  // 1M
    split_kernel<<<NQ / 1024, 256>>>(q, qin_h, qin_l, NQ);
    split_kernel<<<NQ / 1024, 256>>>(k, kin_h, kin_l, NQ);
    split_kernel<<<NQ / 1024, 256>>>(v, vin_h, vin_l, NQ);
    split_kernel<<<NW / 1024, 256>>>(Wq, wq_h, wq_l, NW);
    split_kernel<<<NW / 1024, 256>>>(Wk, wk_h, wk_l, NW);
    split_kernel<<<NW / 1024, 256>>>(Wv, wv_h, wv_l, NW);
    split_kernel<<<NW / 1024, 256>>>(Wo, wo_h, wo_l, NW);

    dim3 gp(D_MODEL / 128, NTOK / 128, 1);   // (8, 32)
    // Q projection (scale 1/sqrt(64) folded in) -> split
    kProjSplit<<<gp, 256, SM_PIPE>>>(qin_h, qin_l, D_MODEL, wq_h, wq_l, D_MODEL,
                                     D_MODEL / 32, 0.125f, nullptr, Qh, Ql, D_MODEL,
                                     0, 0, 0, 0, 0, 0);
    // K projection -> split
    kProjSplit<<<gp, 256, SM_PIPE>>>(kin_h, kin_l, D_MODEL, wk_h, wk_l, D_MODEL,
                                     D_MODEL / 32, 1.0f, nullptr, Kh, Kl, D_MODEL,
                                     0, 0, 0, 0, 0, 0);
    // V projection -> fp32
    kProjF32<<<gp, 256, SM_PIPE>>>(vin_h, vin_l, D_MODEL, wv_h, wv_l, D_MODEL,
                                   D_MODEL / 32, 1.0f, Vf, nullptr, nullptr, D_MODEL,
                                   0, 0, 0, 0, 0, 0);
    // V transpose + split
    vtrans_kernel<<<dim3(SSEQ / 32, DKH / 32, BHN), dim3(32, 8)>>>(Vf, Vth, Vtl);

    // Scores = Qs @ K^T -> fp32 attnw (scale already folded into Q)
    dim3 gqk(SSEQ / 128, SSEQ / 128, BHN);   // (16, 16, 32)
    kProjF32<<<gqk, 256, SM_PIPE>>>(Qh, Ql, D_MODEL, Kh, Kl, D_MODEL,
                                    DKH / 32, 1.0f, attnw, nullptr, nullptr, SSEQ,
                                    (size_t)SSEQ * D_MODEL, DKH,
                                    (size_t)SSEQ * D_MODEL, DKH,
                                    (size_t)NHEAD * SSEQ * SSEQ, (size_t)SSEQ * SSEQ);

    // softmax + P hi/lo split (fused)
    softmax_kernel<<<BHN * SSEQ, 256>>>(attnw, Ph, Pl);

    // attn_out = P @ Vt^T -> split AO  (now fully pipelined)
    dim3 gav(1, SSEQ / 128, BHN);            // (1, 16, 32)
    kAV<<<gav, 256, SM_AV>>>(Ph, Pl, SSEQ, Vth, Vtl, SSEQ,
                             SSEQ / 32, 1.0f, nullptr, AOh, AOl, D_MODEL,
                             (size_t)NHEAD * SSEQ * SSEQ, (size_t)SSEQ * SSEQ,
                             (size_t)BHN / 2 * DKH * SSEQ, (size_t)DKH * SSEQ,
                             (size_t)SSEQ * D_MODEL, DKH);

    // output = AO @ Wo^T -> fp32 d_out
    kProjF32<<<gp, 256, SM_PIPE>>>(AOh, AOl, D_MODEL, wo_h, wo_l, D_MODEL,
                                   D_MODEL / 32, 1.0f, out, nullptr, nullptr, D_MODEL,
                                   0, 0, 0, 0, 0, 0);
}